// round 16
// baseline (speedup 1.0000x reference)
#include <cuda_runtime.h>
#include <cuda_fp16.h>
#include <cstdint>
#include <math.h>

#define B_DIM   4
#define SEQ     2048
#define DIM_IN  1024
#define DIM_OUT 1024
#define DIM3    3072
#define NHEADS  16
#define HD      64
#define NTOK    (B_DIM * SEQ)        // 8192

// ---------------------------------------------------------------------------
// Scratch (__device__ globals: allocation-free rule).  All fp16.
// ---------------------------------------------------------------------------
__device__ __half g_qkvh[(size_t)NTOK * DIM3];     // hi split of qkv
__device__ __half g_qkvl[(size_t)NTOK * DIM3];     // lo split of qkv (Q used)
__device__ __half g_Xh[(size_t)NTOK * DIM_IN];     // X rounded to fp16
__device__ __half g_Ch[(size_t)NTOK * DIM_OUT];    // ctx rounded to fp16
__device__ __half g_Wqkv_h[(size_t)DIM3 * DIM_IN]; // [N][K] hi
__device__ __half g_Wqkv_l[(size_t)DIM3 * DIM_IN]; // [N][K] lo
__device__ __half g_Wout_h[(size_t)DIM_OUT * DIM_OUT];
__device__ __half g_Wout_l[(size_t)DIM_OUT * DIM_OUT];

// ---------------------------------------------------------------------------
// PTX helpers (compute_103-safe: mma.sync / ldmatrix / cp.async only)
// ---------------------------------------------------------------------------
__device__ __forceinline__ uint32_t smem_u32(const void* p) {
    uint32_t a;
    asm("{ .reg .u64 t; cvta.to.shared.u64 t, %1; cvt.u32.u64 %0, t; }"
        : "=r"(a) : "l"(p));
    return a;
}

__device__ __forceinline__ void cp16(uint32_t dst, const void* src) {
    asm volatile("cp.async.cg.shared.global [%0], [%1], 16;"
                 :: "r"(dst), "l"(src));
}
#define CP_COMMIT() asm volatile("cp.async.commit_group;")
#define CP_WAIT1()  asm volatile("cp.async.wait_group 1;")

__device__ __forceinline__ void ldsm4(uint32_t* r, uint32_t addr) {
    asm volatile("ldmatrix.sync.aligned.m8n8.x4.shared.b16 {%0,%1,%2,%3}, [%4];"
                 : "=r"(r[0]), "=r"(r[1]), "=r"(r[2]), "=r"(r[3]) : "r"(addr));
}

__device__ __forceinline__ void ldsm4t(uint32_t* r, uint32_t addr) {
    asm volatile("ldmatrix.sync.aligned.m8n8.x4.trans.shared.b16 {%0,%1,%2,%3}, [%4];"
                 : "=r"(r[0]), "=r"(r[1]), "=r"(r[2]), "=r"(r[3]) : "r"(addr));
}

// NOTE: non-volatile — register-only, semantically pure; lets ptxas schedule
// independent MMAs between dependent (same-accumulator) pairs.
__device__ __forceinline__ void mma16816(float* c, const uint32_t* a, const uint32_t* b) {
    asm("mma.sync.aligned.m16n8k16.row.col.f32.f16.f16.f32 "
        "{%0,%1,%2,%3}, {%4,%5,%6,%7}, {%8,%9}, {%0,%1,%2,%3};"
        : "+f"(c[0]), "+f"(c[1]), "+f"(c[2]), "+f"(c[3])
        : "r"(a[0]), "r"(a[1]), "r"(a[2]), "r"(a[3]), "r"(b[0]), "r"(b[1]));
}

__device__ __forceinline__ uint32_t pack_h2(__half x, __half y) {
    __half2 p = __halves2half2(x, y);
    return *(uint32_t*)&p;
}

__device__ __forceinline__ void split_pack(float x, float y, uint32_t& hi, uint32_t& lo) {
    __half hx = __float2half(x);
    __half hy = __float2half(y);
    __half lx = __float2half(x - __half2float(hx));
    __half ly = __float2half(y - __half2float(hy));
    hi = pack_h2(hx, hy);
    lo = pack_h2(lx, ly);
}

// ---------------------------------------------------------------------------
// Round fp32 -> fp16 (row-major, single array)
// ---------------------------------------------------------------------------
__global__ __launch_bounds__(256)
void round_rows_kernel(const float4* __restrict__ A, int n4, uint2* __restrict__ H) {
    int i = blockIdx.x * 256 + threadIdx.x;
    if (i >= n4) return;
    float4 v = A[i];
    uint2 hh;
    hh.x = pack_h2(__float2half(v.x), __float2half(v.y));
    hh.y = pack_h2(__float2half(v.z), __float2half(v.w));
    H[i] = hh;
}

// ---------------------------------------------------------------------------
// Transpose + split: W [K][N] fp32 -> Th/Tl [N][K] fp16 hi/lo
// ---------------------------------------------------------------------------
__global__ void transpose_split_kernel(const float* __restrict__ W, int K, int N,
                                       __half* __restrict__ Th,
                                       __half* __restrict__ Tl) {
    __shared__ float t[32][33];
    const int n0 = blockIdx.x * 32;
    const int k0 = blockIdx.y * 32;
    const int tx = threadIdx.x, ty = threadIdx.y;   // 32 x 8
#pragma unroll
    for (int i = 0; i < 32; i += 8)
        t[ty + i][tx] = W[(size_t)(k0 + ty + i) * N + n0 + tx];
    __syncthreads();
#pragma unroll
    for (int i = 0; i < 32; i += 8) {
        float v = t[tx][ty + i];
        __half h = __float2half(v);
        __half l = __float2half(v - __half2float(h));
        Th[(size_t)(n0 + ty + i) * K + k0 + tx] = h;
        Tl[(size_t)(n0 + ty + i) * K + k0 + tx] = l;
    }
}

// ---------------------------------------------------------------------------
// HMMA GEMM: C[M,N] = A[M,K](fp16 rounded) @ (Bh+Bl)^T[N,K].
// 128x128 tile, 256 threads, 8 warps (2m x 4n, warp 64x32), 2 CTAs/SM.
// Hi-term MMAs for all 16 accumulators first, then lo-term — no adjacent
// same-accumulator dependencies.
// ---------------------------------------------------------------------------
#define BM 128
#define BN 128
#define BK 32
#define PADK 40
#define T_A  (BM * PADK * 2)          // 10240 B per array
#define STAGE_B (3 * T_A)             // A | Bh | Bl = 30720 B
#define GEMM_SMEM (2 * STAGE_B)       // 61440 B

__global__ __launch_bounds__(256, 2)
void hmma_gemm_kernel(int M, int N, int K,
                      const __half* __restrict__ A,
                      const __half* __restrict__ Bh,
                      const __half* __restrict__ Bl,
                      float* __restrict__ C,
                      const float* __restrict__ bias,
                      __half* __restrict__ Ch,
                      __half* __restrict__ Cl,
                      int scale_cols) {
    extern __shared__ char smem[];
    const uint32_t sbase = smem_u32(smem);
    const int tid  = threadIdx.x;
    const int lane = tid & 31;
    const int wid  = tid >> 5;
    const int m0 = blockIdx.y * BM;
    const int n0 = blockIdx.x * BN;
    const int warp_m = (wid & 1) * 64;
    const int warp_n = (wid >> 1) * 32;

    float c[4][4][4];
#pragma unroll
    for (int i = 0; i < 4; i++)
#pragma unroll
        for (int j = 0; j < 4; j++)
#pragma unroll
            for (int k = 0; k < 4; k++) c[i][j][k] = 0.0f;

    auto load_stage = [&](int s, int kb) {
        const uint32_t st = sbase + s * STAGE_B;
#pragma unroll
        for (int r = 0; r < 2; r++) {
            const int i   = tid + r * 256;
            const int row = i >> 2;
            const int seg = i & 3;
            const uint32_t off = row * (PADK * 2) + seg * 16;
            const size_t ga = (size_t)(m0 + row) * K + kb + seg * 8;
            const size_t gb = (size_t)(n0 + row) * K + kb + seg * 8;
            cp16(st + off,             A + ga);
            cp16(st + T_A + off,       Bh + gb);
            cp16(st + 2 * T_A + off,   Bl + gb);
        }
    };

    const int NKB = K / BK;
    load_stage(0, 0);
    CP_COMMIT();

    for (int kb = 0; kb < NKB; kb++) {
        if (kb + 1 < NKB) load_stage((kb + 1) & 1, (kb + 1) * BK);
        CP_COMMIT();
        CP_WAIT1();
        __syncthreads();

        const uint32_t st = sbase + (kb & 1) * STAGE_B;
#pragma unroll
        for (int ks = 0; ks < 2; ks++) {
            uint32_t ah[4][4], bh[4][2], bl[4][2];
            const int arow = warp_m + (lane & 15);
            const int acol = ks * 16 + (lane >> 4) * 8;
#pragma unroll
            for (int mi = 0; mi < 4; mi++)
                ldsm4(ah[mi], st + ((arow + mi * 16) * PADK + acol) * 2);
            const int bn = ((lane >> 3) & 1) * 8 + (lane & 7);
            const int bk = ks * 16 + (lane >> 4) * 8;
#pragma unroll
            for (int np = 0; np < 2; np++) {
                const uint32_t bd =
                    st + T_A + ((warp_n + np * 16 + bn) * PADK + bk) * 2;
                uint32_t r[4];
                ldsm4(r, bd);
                bh[np * 2 + 0][0] = r[0]; bh[np * 2 + 0][1] = r[2];
                bh[np * 2 + 1][0] = r[1]; bh[np * 2 + 1][1] = r[3];
                ldsm4(r, bd + T_A);
                bl[np * 2 + 0][0] = r[0]; bl[np * 2 + 0][1] = r[2];
                bl[np * 2 + 1][0] = r[1]; bl[np * 2 + 1][1] = r[3];
            }
            // hi-term for all accumulators, then lo-term: 16 independent MMAs
            // between any dependent pair.
#pragma unroll
            for (int mi = 0; mi < 4; mi++)
#pragma unroll
                for (int ni = 0; ni < 4; ni++)
                    mma16816(c[mi][ni], ah[mi], bh[ni]);
#pragma unroll
            for (int mi = 0; mi < 4; mi++)
#pragma unroll
                for (int ni = 0; ni < 4; ni++)
                    mma16816(c[mi][ni], ah[mi], bl[ni]);
        }
        __syncthreads();
    }

    const int erow = m0 + warp_m + (lane >> 2);
    const int ecol = n0 + warp_n + (lane & 3) * 2;
#pragma unroll
    for (int mi = 0; mi < 4; mi++) {
#pragma unroll
        for (int ni = 0; ni < 4; ni++) {
            const int row = erow + mi * 16;
            const int col = ecol + ni * 8;
            if (Ch) {
                const float s = (col < scale_cols) ? 0.125f : 1.0f;
                uint32_t hi, lo;
                split_pack(c[mi][ni][0] * s, c[mi][ni][1] * s, hi, lo);
                *(uint32_t*)(Ch + (size_t)row * N + col) = hi;
                *(uint32_t*)(Cl + (size_t)row * N + col) = lo;
                split_pack(c[mi][ni][2] * s, c[mi][ni][3] * s, hi, lo);
                *(uint32_t*)(Ch + (size_t)(row + 8) * N + col) = hi;
                *(uint32_t*)(Cl + (size_t)(row + 8) * N + col) = lo;
            } else {
                float b0 = 0.0f, b1 = 0.0f;
                if (bias) { b0 = bias[col]; b1 = bias[col + 1]; }
                float2 v0 = make_float2(c[mi][ni][0] + b0, c[mi][ni][1] + b1);
                float2 v1 = make_float2(c[mi][ni][2] + b0, c[mi][ni][3] + b1);
                *(float2*)(C + (size_t)row * N + col)       = v0;
                *(float2*)(C + (size_t)(row + 8) * N + col) = v1;
            }
        }
    }
}

// ---------------------------------------------------------------------------
// HMMA flash attention (fp16, 2-term).  Q exact (hi+lo), K/V single-rounded.
// Q-tile 128, K-tile 64 double-buffered, 8 warps.  V via ldmatrix.trans.
// MMA emission: hi loop then lo loop (8 independent between dependents).
// ---------------------------------------------------------------------------
#define QT 128
#define KT 64
#define APAD 72
#define Q_HALVES  (QT * APAD)
#define KV_HALVES (KT * APAD)
#define STG_HALVES (2 * KV_HALVES)                 // Kh | Vh
#define ATT_SMEM ((2 * Q_HALVES + 2 * STG_HALVES) * 2)   // 73728 B

__global__ __launch_bounds__(256, 2)
void attn_hmma_kernel(const __half* __restrict__ qh,
                      const __half* __restrict__ ql,
                      __half* __restrict__ ch) {
    extern __shared__ char smc[];
    const uint32_t sbase = smem_u32(smc);
    const uint32_t sQh = sbase;
    const uint32_t sQl = sbase + Q_HALVES * 2;

    const int qt = blockIdx.x, h = blockIdx.y, b = blockIdx.z;
    const int tid = threadIdx.x, lane = tid & 31, w = tid >> 5;
    const int q0 = qt * QT;
    const size_t tok0 = (size_t)b * SEQ;

#pragma unroll
    for (int it = 0; it < 4; it++) {
        const int i = tid + it * 256;          // 0..1023
        const int r = i >> 3, seg = i & 7;
        const size_t g = (tok0 + q0 + r) * DIM3 + h * HD + seg * 8;
        const uint32_t off = (r * APAD + seg * 8) * 2;
        cp16(sQh + off, qh + g);
        cp16(sQl + off, ql + g);
    }

    auto load_kv = [&](int s, int kt) {
        const uint32_t st = sbase + (2 * Q_HALVES + s * STG_HALVES) * 2;
#pragma unroll
        for (int it = 0; it < 2; it++) {
            const int i = tid + it * 256;      // 0..511
            const int r = i >> 3, seg = i & 7;
            const size_t g = (tok0 + kt * KT + r) * DIM3 + h * HD + seg * 8;
            const uint32_t off = (r * APAD + seg * 8) * 2;
            cp16(st + off,                  qh + g + DIM_OUT);       // Kh
            cp16(st + KV_HALVES * 2 + off,  qh + g + 2 * DIM_OUT);   // Vh
        }
    };

    load_kv(0, 0);
    CP_COMMIT();

    float o[8][4];
#pragma unroll
    for (int t = 0; t < 8; t++)
#pragma unroll
        for (int j = 0; j < 4; j++) o[t][j] = 0.0f;
    float mrow[2] = {-1e30f, -1e30f};
    float lrow[2] = {0.0f, 0.0f};

    const int nkt = (qt + 1) * 2;
    for (int kt = 0; kt < nkt; kt++) {
        if (kt + 1 < nkt) load_kv((kt + 1) & 1, kt + 1);
        CP_COMMIT();
        CP_WAIT1();
        __syncthreads();

        const uint32_t st  = sbase + (2 * Q_HALVES + (kt & 1) * STG_HALVES) * 2;
        const uint32_t sKh = st;
        const uint32_t sVh = st + KV_HALVES * 2;
        const int k0 = kt * KT;

        // ---- S = (Qh + Ql) @ Kh^T, warp tile 16 x 64 ----
        float sc[8][4];
#pragma unroll
        for (int t = 0; t < 8; t++)
#pragma unroll
            for (int j = 0; j < 4; j++) sc[t][j] = 0.0f;

#pragma unroll
        for (int ks = 0; ks < 4; ks++) {
            const int arow = w * 16 + (lane & 15);
            const int acol = ks * 16 + (lane >> 4) * 8;
            uint32_t ah[4], al[4];
            ldsm4(ah, sQh + (arow * APAD + acol) * 2);
            ldsm4(al, sQl + (arow * APAD + acol) * 2);
            uint32_t bh[8][2];
            const int bn = ((lane >> 3) & 1) * 8 + (lane & 7);
#pragma unroll
            for (int np = 0; np < 4; np++) {
                const uint32_t off = ((np * 16 + bn) * APAD + acol) * 2;
                uint32_t r[4];
                ldsm4(r, sKh + off);
                bh[np * 2 + 0][0] = r[0]; bh[np * 2 + 0][1] = r[2];
                bh[np * 2 + 1][0] = r[1]; bh[np * 2 + 1][1] = r[3];
            }
#pragma unroll
            for (int t = 0; t < 8; t++)
                mma16816(sc[t], ah, bh[t]);
#pragma unroll
            for (int t = 0; t < 8; t++)
                mma16816(sc[t], al, bh[t]);
        }

        // ---- causal mask (near-diagonal tiles only) ----
        const int row0 = q0 + w * 16 + (lane >> 2);
        if (k0 + KT - 1 > q0 + w * 16) {
#pragma unroll
            for (int t = 0; t < 8; t++) {
                const int col = k0 + t * 8 + (lane & 3) * 2;
                if (col     > row0)     sc[t][0] = -1e30f;
                if (col + 1 > row0)     sc[t][1] = -1e30f;
                if (col     > row0 + 8) sc[t][2] = -1e30f;
                if (col + 1 > row0 + 8) sc[t][3] = -1e30f;
            }
        }

        // ---- online softmax ----
#pragma unroll
        for (int rh = 0; rh < 2; rh++) {
            const int i0 = rh * 2;
            float mx = -1e30f;
#pragma unroll
            for (int t = 0; t < 8; t++)
                mx = fmaxf(mx, fmaxf(sc[t][i0], sc[t][i0 + 1]));
            mx = fmaxf(mx, __shfl_xor_sync(0xffffffffu, mx, 1));
            mx = fmaxf(mx, __shfl_xor_sync(0xffffffffu, mx, 2));
            const float mn = fmaxf(mrow[rh], mx);
            const float alpha = __expf(mrow[rh] - mn);
            float rs = 0.0f;
#pragma unroll
            for (int t = 0; t < 8; t++) {
                const float p0 = __expf(sc[t][i0] - mn);
                const float p1 = __expf(sc[t][i0 + 1] - mn);
                sc[t][i0] = p0; sc[t][i0 + 1] = p1;
                rs += p0 + p1;
            }
            rs += __shfl_xor_sync(0xffffffffu, rs, 1);
            rs += __shfl_xor_sync(0xffffffffu, rs, 2);
            lrow[rh] = lrow[rh] * alpha + rs;
            mrow[rh] = mn;
#pragma unroll
            for (int t = 0; t < 8; t++) { o[t][i0] *= alpha; o[t][i0 + 1] *= alpha; }
        }

        // ---- O += (Ph + Pl) @ Vh; V via ldmatrix.trans ----
#pragma unroll
        for (int ks = 0; ks < 4; ks++) {
            uint32_t ph[4], pl[4];
            split_pack(sc[2 * ks][0],     sc[2 * ks][1],     ph[0], pl[0]);
            split_pack(sc[2 * ks][2],     sc[2 * ks][3],     ph[1], pl[1]);
            split_pack(sc[2 * ks + 1][0], sc[2 * ks + 1][1], ph[2], pl[2]);
            split_pack(sc[2 * ks + 1][2], sc[2 * ks + 1][3], ph[3], pl[3]);

            uint32_t vh[8][2];
            const int kvrow = ks * 16 + (lane & 15);
            const int dcol  = (lane >> 4) * 8;
#pragma unroll
            for (int np = 0; np < 4; np++) {
                const uint32_t off = (kvrow * APAD + np * 16 + dcol) * 2;
                uint32_t r[4];
                ldsm4t(r, sVh + off);
                vh[np * 2 + 0][0] = r[0]; vh[np * 2 + 0][1] = r[1];
                vh[np * 2 + 1][0] = r[2]; vh[np * 2 + 1][1] = r[3];
            }
#pragma unroll
            for (int t = 0; t < 8; t++)
                mma16816(o[t], ph, vh[t]);
#pragma unroll
            for (int t = 0; t < 8; t++)
                mma16816(o[t], pl, vh[t]);
        }
        __syncthreads();
    }

    // ---- normalize + single-rounded fp16 ctx write ----
    const float inv0 = 1.0f / lrow[0];
    const float inv1 = 1.0f / lrow[1];
    const size_t row0 = tok0 + q0 + w * 16 + (lane >> 2);
#pragma unroll
    for (int t = 0; t < 8; t++) {
        const int col = h * HD + t * 8 + (lane & 3) * 2;
        *(uint32_t*)(ch + row0 * DIM_OUT + col) =
            pack_h2(__float2half(o[t][0] * inv0), __float2half(o[t][1] * inv0));
        *(uint32_t*)(ch + (row0 + 8) * DIM_OUT + col) =
            pack_h2(__float2half(o[t][2] * inv1), __float2half(o[t][3] * inv1));
    }
}

// ---------------------------------------------------------------------------
extern "C" void kernel_launch(void* const* d_in, const int* in_sizes, int n_in,
                              void* d_out, int out_size) {
    const float* X     = (const float*)d_in[0];
    const float* W_qkv = (const float*)d_in[1];
    const float* W_out = (const float*)d_in[2];
    const float* b_out = (const float*)d_in[3];
    float* out = (float*)d_out;

    __half *qkvh, *qkvl, *xh, *ch, *wqh, *wql, *woh, *wol;
    cudaGetSymbolAddress((void**)&qkvh, g_qkvh);
    cudaGetSymbolAddress((void**)&qkvl, g_qkvl);
    cudaGetSymbolAddress((void**)&xh,  g_Xh);
    cudaGetSymbolAddress((void**)&ch,  g_Ch);
    cudaGetSymbolAddress((void**)&wqh, g_Wqkv_h);
    cudaGetSymbolAddress((void**)&wql, g_Wqkv_l);
    cudaGetSymbolAddress((void**)&woh, g_Wout_h);
    cudaGetSymbolAddress((void**)&wol, g_Wout_l);

    cudaFuncSetAttribute(hmma_gemm_kernel,
                         cudaFuncAttributeMaxDynamicSharedMemorySize, GEMM_SMEM);
    cudaFuncSetAttribute(attn_hmma_kernel,
                         cudaFuncAttributeMaxDynamicSharedMemorySize, ATT_SMEM);

    // 0) weight transpose+split (fp16 hi/lo), X round (fp16)
    {
        dim3 blk(32, 8);
        transpose_split_kernel<<<dim3(DIM3 / 32, DIM_IN / 32), blk>>>(
            W_qkv, DIM_IN, DIM3, wqh, wql);
        transpose_split_kernel<<<dim3(DIM_OUT / 32, DIM_OUT / 32), blk>>>(
            W_out, DIM_OUT, DIM_OUT, woh, wol);
        const int n4 = NTOK * DIM_IN / 4;
        round_rows_kernel<<<(n4 + 255) / 256, 256>>>(
            (const float4*)X, n4, (uint2*)xh);
    }

    // 1) QKV projection -> split fp16 qkv (Q cols pre-scaled by 0.125)
    hmma_gemm_kernel<<<dim3(DIM3 / BN, NTOK / BM), 256, GEMM_SMEM>>>(
        NTOK, DIM3, DIM_IN, xh, wqh, wql,
        nullptr, nullptr, qkvh, qkvl, DIM_OUT);

    // 2) causal flash attention -> single-rounded fp16 ctx
    attn_hmma_kernel<<<dim3(SEQ / QT, NHEADS, B_DIM), 256, ATT_SMEM>>>(
        qkvh, qkvl, ch);

    // 3) out projection + bias -> fp32 output
    hmma_gemm_kernel<<<dim3(DIM_OUT / BN, NTOK / BM), 256, GEMM_SMEM>>>(
        NTOK, DIM_OUT, DIM_OUT, ch, woh, wol,
        out, b_out, nullptr, nullptr, 0);
}

// round 17
// speedup vs baseline: 1.2345x; 1.2345x over previous
#include <cuda_runtime.h>
#include <cuda_fp16.h>
#include <cstdint>
#include <math.h>

#define B_DIM   4
#define SEQ     2048
#define DIM_IN  1024
#define DIM_OUT 1024
#define DIM3    3072
#define NHEADS  16
#define HD      64
#define NTOK    (B_DIM * SEQ)        // 8192

// ---------------------------------------------------------------------------
// Scratch (__device__ globals: allocation-free rule).  All fp16.
// ---------------------------------------------------------------------------
__device__ __half g_qkvh[(size_t)NTOK * DIM3];     // hi split of qkv
__device__ __half g_qkvl[(size_t)NTOK * DIM3];     // lo split (Q cols only)
__device__ __half g_Xh[(size_t)NTOK * DIM_IN];     // X rounded to fp16
__device__ __half g_Ch[(size_t)NTOK * DIM_OUT];    // ctx rounded to fp16
__device__ __half g_Wqkv_h[(size_t)DIM3 * DIM_IN]; // [N][K] hi
__device__ __half g_Wqkv_l[(size_t)DIM3 * DIM_IN]; // [N][K] lo
__device__ __half g_Wout_h[(size_t)DIM_OUT * DIM_OUT];

// ---------------------------------------------------------------------------
// PTX helpers (compute_103-safe: mma.sync / ldmatrix / cp.async only)
// ---------------------------------------------------------------------------
__device__ __forceinline__ uint32_t smem_u32(const void* p) {
    uint32_t a;
    asm("{ .reg .u64 t; cvta.to.shared.u64 t, %1; cvt.u32.u64 %0, t; }"
        : "=r"(a) : "l"(p));
    return a;
}

__device__ __forceinline__ void cp16(uint32_t dst, const void* src) {
    asm volatile("cp.async.cg.shared.global [%0], [%1], 16;"
                 :: "r"(dst), "l"(src));
}
#define CP_COMMIT() asm volatile("cp.async.commit_group;")
#define CP_WAIT1()  asm volatile("cp.async.wait_group 1;")

__device__ __forceinline__ void ldsm4(uint32_t* r, uint32_t addr) {
    asm volatile("ldmatrix.sync.aligned.m8n8.x4.shared.b16 {%0,%1,%2,%3}, [%4];"
                 : "=r"(r[0]), "=r"(r[1]), "=r"(r[2]), "=r"(r[3]) : "r"(addr));
}

__device__ __forceinline__ void ldsm4t(uint32_t* r, uint32_t addr) {
    asm volatile("ldmatrix.sync.aligned.m8n8.x4.trans.shared.b16 {%0,%1,%2,%3}, [%4];"
                 : "=r"(r[0]), "=r"(r[1]), "=r"(r[2]), "=r"(r[3]) : "r"(addr));
}

__device__ __forceinline__ void mma16816(float* c, const uint32_t* a, const uint32_t* b) {
    asm("mma.sync.aligned.m16n8k16.row.col.f32.f16.f16.f32 "
        "{%0,%1,%2,%3}, {%4,%5,%6,%7}, {%8,%9}, {%0,%1,%2,%3};"
        : "+f"(c[0]), "+f"(c[1]), "+f"(c[2]), "+f"(c[3])
        : "r"(a[0]), "r"(a[1]), "r"(a[2]), "r"(a[3]), "r"(b[0]), "r"(b[1]));
}

__device__ __forceinline__ uint32_t pack_h2(__half x, __half y) {
    __half2 p = __halves2half2(x, y);
    return *(uint32_t*)&p;
}

__device__ __forceinline__ uint32_t round_pack(float x, float y) {
    return pack_h2(__float2half(x), __float2half(y));
}

__device__ __forceinline__ void split_pack(float x, float y, uint32_t& hi, uint32_t& lo) {
    __half hx = __float2half(x);
    __half hy = __float2half(y);
    __half lx = __float2half(x - __half2float(hx));
    __half ly = __float2half(y - __half2float(hy));
    hi = pack_h2(hx, hy);
    lo = pack_h2(lx, ly);
}

// ---------------------------------------------------------------------------
// Round fp32 -> fp16 (row-major, single array)
// ---------------------------------------------------------------------------
__global__ __launch_bounds__(256)
void round_rows_kernel(const float4* __restrict__ A, int n4, uint2* __restrict__ H) {
    int i = blockIdx.x * 256 + threadIdx.x;
    if (i >= n4) return;
    float4 v = A[i];
    uint2 hh;
    hh.x = round_pack(v.x, v.y);
    hh.y = round_pack(v.z, v.w);
    H[i] = hh;
}

// ---------------------------------------------------------------------------
// Transpose + split: W [K][N] fp32 -> Th (and optionally Tl) [N][K] fp16
// ---------------------------------------------------------------------------
__global__ void transpose_split_kernel(const float* __restrict__ W, int K, int N,
                                       __half* __restrict__ Th,
                                       __half* __restrict__ Tl) {
    __shared__ float t[32][33];
    const int n0 = blockIdx.x * 32;
    const int k0 = blockIdx.y * 32;
    const int tx = threadIdx.x, ty = threadIdx.y;   // 32 x 8
#pragma unroll
    for (int i = 0; i < 32; i += 8)
        t[ty + i][tx] = W[(size_t)(k0 + ty + i) * N + n0 + tx];
    __syncthreads();
#pragma unroll
    for (int i = 0; i < 32; i += 8) {
        float v = t[tx][ty + i];
        __half h = __float2half(v);
        Th[(size_t)(n0 + ty + i) * K + k0 + tx] = h;
        if (Tl)
            Tl[(size_t)(n0 + ty + i) * K + k0 + tx] =
                __float2half(v - __half2float(h));
    }
}

// ---------------------------------------------------------------------------
// HMMA GEMM: C[M,N] = A[M,K](fp16 rounded) @ (Bh[+Bl])^T[N,K].
// 128x128 tile, 256 threads, 8 warps (2m x 4n, warp 64x32), 2 CTAs/SM.
// Lo-term (A*Bl) only for output columns < lo_cols (tile-uniform branch).
// Epilogue: fp32(+bias) to C, or fp16 hi(/lo for cols < losplit_cols) to
// Ch/Cl, with cols < scale_cols scaled by 0.125 (exact pow2).
// ---------------------------------------------------------------------------
#define BM 128
#define BN 128
#define BK 32
#define PADK 40
#define T_A  (BM * PADK * 2)          // 10240 B per array
#define STAGE_B (3 * T_A)             // A | Bh | Bl = 30720 B
#define GEMM_SMEM (2 * STAGE_B)       // 61440 B

__global__ __launch_bounds__(256, 2)
void hmma_gemm_kernel(int M, int N, int K,
                      const __half* __restrict__ A,
                      const __half* __restrict__ Bh,
                      const __half* __restrict__ Bl,
                      float* __restrict__ C,
                      const float* __restrict__ bias,
                      __half* __restrict__ Ch,
                      __half* __restrict__ Cl,
                      int scale_cols,
                      int lo_cols,
                      int losplit_cols) {
    extern __shared__ char smem[];
    const uint32_t sbase = smem_u32(smem);
    const int tid  = threadIdx.x;
    const int lane = tid & 31;
    const int wid  = tid >> 5;
    const int m0 = blockIdx.y * BM;
    const int n0 = blockIdx.x * BN;
    const int warp_m = (wid & 1) * 64;
    const int warp_n = (wid >> 1) * 32;
    const bool use_lo = (n0 < lo_cols);

    float c[4][4][4];
#pragma unroll
    for (int i = 0; i < 4; i++)
#pragma unroll
        for (int j = 0; j < 4; j++)
#pragma unroll
            for (int k = 0; k < 4; k++) c[i][j][k] = 0.0f;

    auto load_stage = [&](int s, int kb) {
        const uint32_t st = sbase + s * STAGE_B;
#pragma unroll
        for (int r = 0; r < 2; r++) {
            const int i   = tid + r * 256;
            const int row = i >> 2;
            const int seg = i & 3;
            const uint32_t off = row * (PADK * 2) + seg * 16;
            const size_t ga = (size_t)(m0 + row) * K + kb + seg * 8;
            const size_t gb = (size_t)(n0 + row) * K + kb + seg * 8;
            cp16(st + off,             A + ga);
            cp16(st + T_A + off,       Bh + gb);
            if (use_lo) cp16(st + 2 * T_A + off, Bl + gb);
        }
    };

    const int NKB = K / BK;
    load_stage(0, 0);
    CP_COMMIT();

    for (int kb = 0; kb < NKB; kb++) {
        if (kb + 1 < NKB) load_stage((kb + 1) & 1, (kb + 1) * BK);
        CP_COMMIT();
        CP_WAIT1();
        __syncthreads();

        const uint32_t st = sbase + (kb & 1) * STAGE_B;
#pragma unroll
        for (int ks = 0; ks < 2; ks++) {
            uint32_t ah[4][4], bh[4][2], bl[4][2];
            const int arow = warp_m + (lane & 15);
            const int acol = ks * 16 + (lane >> 4) * 8;
#pragma unroll
            for (int mi = 0; mi < 4; mi++)
                ldsm4(ah[mi], st + ((arow + mi * 16) * PADK + acol) * 2);
            const int bn = ((lane >> 3) & 1) * 8 + (lane & 7);
            const int bk = ks * 16 + (lane >> 4) * 8;
#pragma unroll
            for (int np = 0; np < 2; np++) {
                const uint32_t bd =
                    st + T_A + ((warp_n + np * 16 + bn) * PADK + bk) * 2;
                uint32_t r[4];
                ldsm4(r, bd);
                bh[np * 2 + 0][0] = r[0]; bh[np * 2 + 0][1] = r[2];
                bh[np * 2 + 1][0] = r[1]; bh[np * 2 + 1][1] = r[3];
            }
            if (use_lo) {
#pragma unroll
                for (int np = 0; np < 2; np++) {
                    const uint32_t bd =
                        st + 2 * T_A + ((warp_n + np * 16 + bn) * PADK + bk) * 2;
                    uint32_t r[4];
                    ldsm4(r, bd);
                    bl[np * 2 + 0][0] = r[0]; bl[np * 2 + 0][1] = r[2];
                    bl[np * 2 + 1][0] = r[1]; bl[np * 2 + 1][1] = r[3];
                }
            }
#pragma unroll
            for (int mi = 0; mi < 4; mi++)
#pragma unroll
                for (int ni = 0; ni < 4; ni++)
                    mma16816(c[mi][ni], ah[mi], bh[ni]);
            if (use_lo) {
#pragma unroll
                for (int mi = 0; mi < 4; mi++)
#pragma unroll
                    for (int ni = 0; ni < 4; ni++)
                        mma16816(c[mi][ni], ah[mi], bl[ni]);
            }
        }
        __syncthreads();
    }

    const int erow = m0 + warp_m + (lane >> 2);
    const int ecol = n0 + warp_n + (lane & 3) * 2;
#pragma unroll
    for (int mi = 0; mi < 4; mi++) {
#pragma unroll
        for (int ni = 0; ni < 4; ni++) {
            const int row = erow + mi * 16;
            const int col = ecol + ni * 8;
            if (Ch) {
                const float s = (col < scale_cols) ? 0.125f : 1.0f;
                uint32_t hi, lo;
                split_pack(c[mi][ni][0] * s, c[mi][ni][1] * s, hi, lo);
                *(uint32_t*)(Ch + (size_t)row * N + col) = hi;
                if (col < losplit_cols)
                    *(uint32_t*)(Cl + (size_t)row * N + col) = lo;
                split_pack(c[mi][ni][2] * s, c[mi][ni][3] * s, hi, lo);
                *(uint32_t*)(Ch + (size_t)(row + 8) * N + col) = hi;
                if (col < losplit_cols)
                    *(uint32_t*)(Cl + (size_t)(row + 8) * N + col) = lo;
            } else {
                float b0 = 0.0f, b1 = 0.0f;
                if (bias) { b0 = bias[col]; b1 = bias[col + 1]; }
                float2 v0 = make_float2(c[mi][ni][0] + b0, c[mi][ni][1] + b1);
                float2 v1 = make_float2(c[mi][ni][2] + b0, c[mi][ni][3] + b1);
                *(float2*)(C + (size_t)row * N + col)       = v0;
                *(float2*)(C + (size_t)(row + 8) * N + col) = v1;
            }
        }
    }
}

// ---------------------------------------------------------------------------
// HMMA flash attention.  Q exact (hi+lo), K/V single-rounded, P single-
// rounded (lo dropped — linear error path).  Q-tile 128, K-tile 64 double-
// buffered, 8 warps.  V via ldmatrix.trans.
// ---------------------------------------------------------------------------
#define QT 128
#define KT 64
#define APAD 72
#define Q_HALVES  (QT * APAD)
#define KV_HALVES (KT * APAD)
#define STG_HALVES (2 * KV_HALVES)                 // Kh | Vh
#define ATT_SMEM ((2 * Q_HALVES + 2 * STG_HALVES) * 2)   // 73728 B

__global__ __launch_bounds__(256, 2)
void attn_hmma_kernel(const __half* __restrict__ qh,
                      const __half* __restrict__ ql,
                      __half* __restrict__ ch) {
    extern __shared__ char smc[];
    const uint32_t sbase = smem_u32(smc);
    const uint32_t sQh = sbase;
    const uint32_t sQl = sbase + Q_HALVES * 2;

    const int qt = blockIdx.x, h = blockIdx.y, b = blockIdx.z;
    const int tid = threadIdx.x, lane = tid & 31, w = tid >> 5;
    const int q0 = qt * QT;
    const size_t tok0 = (size_t)b * SEQ;

#pragma unroll
    for (int it = 0; it < 4; it++) {
        const int i = tid + it * 256;          // 0..1023
        const int r = i >> 3, seg = i & 7;
        const size_t g = (tok0 + q0 + r) * DIM3 + h * HD + seg * 8;
        const uint32_t off = (r * APAD + seg * 8) * 2;
        cp16(sQh + off, qh + g);
        cp16(sQl + off, ql + g);
    }

    auto load_kv = [&](int s, int kt) {
        const uint32_t st = sbase + (2 * Q_HALVES + s * STG_HALVES) * 2;
#pragma unroll
        for (int it = 0; it < 2; it++) {
            const int i = tid + it * 256;      // 0..511
            const int r = i >> 3, seg = i & 7;
            const size_t g = (tok0 + kt * KT + r) * DIM3 + h * HD + seg * 8;
            const uint32_t off = (r * APAD + seg * 8) * 2;
            cp16(st + off,                  qh + g + DIM_OUT);       // Kh
            cp16(st + KV_HALVES * 2 + off,  qh + g + 2 * DIM_OUT);   // Vh
        }
    };

    load_kv(0, 0);
    CP_COMMIT();

    float o[8][4];
#pragma unroll
    for (int t = 0; t < 8; t++)
#pragma unroll
        for (int j = 0; j < 4; j++) o[t][j] = 0.0f;
    float mrow[2] = {-1e30f, -1e30f};
    float lrow[2] = {0.0f, 0.0f};

    const int nkt = (qt + 1) * 2;
    for (int kt = 0; kt < nkt; kt++) {
        if (kt + 1 < nkt) load_kv((kt + 1) & 1, kt + 1);
        CP_COMMIT();
        CP_WAIT1();
        __syncthreads();

        const uint32_t st  = sbase + (2 * Q_HALVES + (kt & 1) * STG_HALVES) * 2;
        const uint32_t sKh = st;
        const uint32_t sVh = st + KV_HALVES * 2;
        const int k0 = kt * KT;

        // ---- S = (Qh + Ql) @ Kh^T, warp tile 16 x 64 ----
        float sc[8][4];
#pragma unroll
        for (int t = 0; t < 8; t++)
#pragma unroll
            for (int j = 0; j < 4; j++) sc[t][j] = 0.0f;

#pragma unroll
        for (int ks = 0; ks < 4; ks++) {
            const int arow = w * 16 + (lane & 15);
            const int acol = ks * 16 + (lane >> 4) * 8;
            uint32_t ah[4], al[4];
            ldsm4(ah, sQh + (arow * APAD + acol) * 2);
            ldsm4(al, sQl + (arow * APAD + acol) * 2);
            uint32_t bh[8][2];
            const int bn = ((lane >> 3) & 1) * 8 + (lane & 7);
#pragma unroll
            for (int np = 0; np < 4; np++) {
                const uint32_t off = ((np * 16 + bn) * APAD + acol) * 2;
                uint32_t r[4];
                ldsm4(r, sKh + off);
                bh[np * 2 + 0][0] = r[0]; bh[np * 2 + 0][1] = r[2];
                bh[np * 2 + 1][0] = r[1]; bh[np * 2 + 1][1] = r[3];
            }
#pragma unroll
            for (int t = 0; t < 8; t++)
                mma16816(sc[t], ah, bh[t]);
#pragma unroll
            for (int t = 0; t < 8; t++)
                mma16816(sc[t], al, bh[t]);
        }

        // ---- causal mask (near-diagonal tiles only) ----
        const int row0 = q0 + w * 16 + (lane >> 2);
        if (k0 + KT - 1 > q0 + w * 16) {
#pragma unroll
            for (int t = 0; t < 8; t++) {
                const int col = k0 + t * 8 + (lane & 3) * 2;
                if (col     > row0)     sc[t][0] = -1e30f;
                if (col + 1 > row0)     sc[t][1] = -1e30f;
                if (col     > row0 + 8) sc[t][2] = -1e30f;
                if (col + 1 > row0 + 8) sc[t][3] = -1e30f;
            }
        }

        // ---- online softmax ----
#pragma unroll
        for (int rh = 0; rh < 2; rh++) {
            const int i0 = rh * 2;
            float mx = -1e30f;
#pragma unroll
            for (int t = 0; t < 8; t++)
                mx = fmaxf(mx, fmaxf(sc[t][i0], sc[t][i0 + 1]));
            mx = fmaxf(mx, __shfl_xor_sync(0xffffffffu, mx, 1));
            mx = fmaxf(mx, __shfl_xor_sync(0xffffffffu, mx, 2));
            const float mn = fmaxf(mrow[rh], mx);
            const float alpha = __expf(mrow[rh] - mn);
            float rs = 0.0f;
#pragma unroll
            for (int t = 0; t < 8; t++) {
                const float p0 = __expf(sc[t][i0] - mn);
                const float p1 = __expf(sc[t][i0 + 1] - mn);
                sc[t][i0] = p0; sc[t][i0 + 1] = p1;
                rs += p0 + p1;
            }
            rs += __shfl_xor_sync(0xffffffffu, rs, 1);
            rs += __shfl_xor_sync(0xffffffffu, rs, 2);
            lrow[rh] = lrow[rh] * alpha + rs;
            mrow[rh] = mn;
#pragma unroll
            for (int t = 0; t < 8; t++) { o[t][i0] *= alpha; o[t][i0 + 1] *= alpha; }
        }

        // ---- O += P @ Vh (P single-rounded); V via ldmatrix.trans ----
#pragma unroll
        for (int ks = 0; ks < 4; ks++) {
            uint32_t ph[4];
            ph[0] = round_pack(sc[2 * ks][0],     sc[2 * ks][1]);
            ph[1] = round_pack(sc[2 * ks][2],     sc[2 * ks][3]);
            ph[2] = round_pack(sc[2 * ks + 1][0], sc[2 * ks + 1][1]);
            ph[3] = round_pack(sc[2 * ks + 1][2], sc[2 * ks + 1][3]);

            uint32_t vh[8][2];
            const int kvrow = ks * 16 + (lane & 15);
            const int dcol  = (lane >> 4) * 8;
#pragma unroll
            for (int np = 0; np < 4; np++) {
                const uint32_t off = (kvrow * APAD + np * 16 + dcol) * 2;
                uint32_t r[4];
                ldsm4t(r, sVh + off);
                vh[np * 2 + 0][0] = r[0]; vh[np * 2 + 0][1] = r[1];
                vh[np * 2 + 1][0] = r[2]; vh[np * 2 + 1][1] = r[3];
            }
#pragma unroll
            for (int t = 0; t < 8; t++)
                mma16816(o[t], ph, vh[t]);
        }
        __syncthreads();
    }

    // ---- normalize + single-rounded fp16 ctx write ----
    const float inv0 = 1.0f / lrow[0];
    const float inv1 = 1.0f / lrow[1];
    const size_t row0 = tok0 + q0 + w * 16 + (lane >> 2);
#pragma unroll
    for (int t = 0; t < 8; t++) {
        const int col = h * HD + t * 8 + (lane & 3) * 2;
        *(uint32_t*)(ch + row0 * DIM_OUT + col) =
            round_pack(o[t][0] * inv0, o[t][1] * inv0);
        *(uint32_t*)(ch + (row0 + 8) * DIM_OUT + col) =
            round_pack(o[t][2] * inv1, o[t][3] * inv1);
    }
}

// ---------------------------------------------------------------------------
extern "C" void kernel_launch(void* const* d_in, const int* in_sizes, int n_in,
                              void* d_out, int out_size) {
    const float* X     = (const float*)d_in[0];
    const float* W_qkv = (const float*)d_in[1];
    const float* W_out = (const float*)d_in[2];
    const float* b_out = (const float*)d_in[3];
    float* out = (float*)d_out;

    __half *qkvh, *qkvl, *xh, *ch, *wqh, *wql, *woh;
    cudaGetSymbolAddress((void**)&qkvh, g_qkvh);
    cudaGetSymbolAddress((void**)&qkvl, g_qkvl);
    cudaGetSymbolAddress((void**)&xh,  g_Xh);
    cudaGetSymbolAddress((void**)&ch,  g_Ch);
    cudaGetSymbolAddress((void**)&wqh, g_Wqkv_h);
    cudaGetSymbolAddress((void**)&wql, g_Wqkv_l);
    cudaGetSymbolAddress((void**)&woh, g_Wout_h);

    cudaFuncSetAttribute(hmma_gemm_kernel,
                         cudaFuncAttributeMaxDynamicSharedMemorySize, GEMM_SMEM);
    cudaFuncSetAttribute(attn_hmma_kernel,
                         cudaFuncAttributeMaxDynamicSharedMemorySize, ATT_SMEM);

    // 0) weight transpose+split (W_qkv hi/lo, W_out hi only), X round
    {
        dim3 blk(32, 8);
        transpose_split_kernel<<<dim3(DIM3 / 32, DIM_IN / 32), blk>>>(
            W_qkv, DIM_IN, DIM3, wqh, wql);
        transpose_split_kernel<<<dim3(DIM_OUT / 32, DIM_OUT / 32), blk>>>(
            W_out, DIM_OUT, DIM_OUT, woh, nullptr);
        const int n4 = NTOK * DIM_IN / 4;
        round_rows_kernel<<<(n4 + 255) / 256, 256>>>(
            (const float4*)X, n4, (uint2*)xh);
    }

    // 1) QKV projection -> split fp16 qkv.
    //    lo-term MMAs only for Q/K cols (< 2048); V cols single-term.
    //    Q cols (< 1024) pre-scaled by 0.125; qkv-lo stored for Q cols only.
    hmma_gemm_kernel<<<dim3(DIM3 / BN, NTOK / BM), 256, GEMM_SMEM>>>(
        NTOK, DIM3, DIM_IN, xh, wqh, wql,
        nullptr, nullptr, qkvh, qkvl,
        /*scale_cols=*/DIM_OUT, /*lo_cols=*/2 * DIM_OUT, /*losplit_cols=*/DIM_OUT);

    // 2) causal flash attention -> single-rounded fp16 ctx
    attn_hmma_kernel<<<dim3(SEQ / QT, NHEADS, B_DIM), 256, ATT_SMEM>>>(
        qkvh, qkvl, ch);

    // 3) out projection + bias -> fp32 output (hi term only)
    hmma_gemm_kernel<<<dim3(DIM_OUT / BN, NTOK / BM), 256, GEMM_SMEM>>>(
        NTOK, DIM_OUT, DIM_OUT, ch, woh, nullptr,
        out, b_out, nullptr, nullptr,
        /*scale_cols=*/0, /*lo_cols=*/0, /*losplit_cols=*/0);
}